// round 13
// baseline (speedup 1.0000x reference)
#include <cuda_runtime.h>
#include <cuda_fp16.h>

// LinearInterpolator: B=8, grid 64^3 fp32, M=96^3 query points, trilinear.
// inputs: d_in[0]=y (8*64^3 fp32), d_in[1]=xnew (8*M*3 fp32)
// output: d_out = 8*M fp32
//
// fp16 8-corner pack (16B/cell, 32 MB, L2-resident) + single LDG.128 gather
// per point (interp is at its L1tex wavefront floor; R11/R12 showed deeper
// MLP attempts regress). This round overlaps prepack with interp via a
// forked capture stream, chunked 2 batches at a time.

static constexpr int B_ = 8;
static constexpr int D_ = 64;
static constexpr int GRID3 = D_ * D_ * D_;        // 262144 = 2^18
static constexpr int M_ = 96 * 96 * 96;           // 884736
static constexpr int PPT = 4;                     // points per thread (interp)
static constexpr int BATCHES_PER_CHUNK = 2;
static constexpr int N_CHUNKS = B_ / BATCHES_PER_CHUNK;   // 4

// cell layout (16B): h2{c000,c001} h2{c010,c011} h2{c100,c101} h2{c110,c111}
__device__ uint4 g_pack[B_ * GRID3];              // 32 MB static scratch

__device__ __forceinline__ unsigned pack2(float a, float b)
{
    __half2 h = __floats2half2_rn(a, b);
    return *reinterpret_cast<unsigned*>(&h);
}

// One block per (batch, i0) plane pair, smem-tiled. b = b0 + blockIdx.x>>6.
__global__ __launch_bounds__(256)
void prepack_kernel(const float* __restrict__ y, int b0)
{
    __shared__ float P0[D_ * D_];
    __shared__ float P1[D_ * D_];

    const int b  = b0 + (blockIdx.x >> 6);
    const int i0 = blockIdx.x & 63;
    const int i0p = min(i0 + 1, D_ - 1);
    const int tid = threadIdx.x;

    const float4* __restrict__ pl0 = reinterpret_cast<const float4*>(y + ((size_t)b << 18) + (i0  << 12));
    const float4* __restrict__ pl1 = reinterpret_cast<const float4*>(y + ((size_t)b << 18) + (i0p << 12));
    float4* s0 = reinterpret_cast<float4*>(P0);
    float4* s1 = reinterpret_cast<float4*>(P1);
#pragma unroll
    for (int k = 0; k < 4; k++) {
        s0[tid + 256 * k] = pl0[tid + 256 * k];
        s1[tid + 256 * k] = pl1[tid + 256 * k];
    }
    __syncthreads();

    const int i2  = tid & 63;
    const int i2p = min(i2 + 1, D_ - 1);
    const int i1b = (tid >> 6) << 4;              // 0,16,32,48

    uint4* __restrict__ dst = g_pack + ((size_t)b << 18) + (i0 << 12) + (i1b << 6) + i2;

    float a0 = P0[(i1b << 6) + i2],  a1 = P0[(i1b << 6) + i2p];
    float e0 = P1[(i1b << 6) + i2],  e1 = P1[(i1b << 6) + i2p];

#pragma unroll
    for (int j = 0; j < 16; j++) {
        const int i1  = i1b + j;
        const int i1n = min(i1 + 1, D_ - 1);
        const float c0 = P0[(i1n << 6) + i2], c1 = P0[(i1n << 6) + i2p];
        const float d0 = P1[(i1n << 6) + i2], d1 = P1[(i1n << 6) + i2p];

        uint4 cc;
        cc.x = pack2(a0, a1);     // c000, c001
        cc.y = pack2(c0, c1);     // c010, c011
        cc.z = pack2(e0, e1);     // c100, c101
        cc.w = pack2(d0, d1);     // c110, c111
        dst[j << 6] = cc;

        a0 = c0; a1 = c1; e0 = d0; e1 = d1;
    }
}

// Interp over one 2-batch chunk. tbase = chunk * (2*M/PPT).
__global__ __launch_bounds__(256)
void interp_kernel(const float* __restrict__ xnew,
                   float* __restrict__ out, int tbase)
{
    const int t = tbase + blockIdx.x * blockDim.x + threadIdx.x;

    const int p0 = t * PPT;
    const int b  = p0 / M_;                       // M_ % 4 == 0: same batch
    const uint4* __restrict__ cp = g_pack + ((size_t)b << 18);

    const float4* __restrict__ xv = reinterpret_cast<const float4*>(xnew) + (size_t)t * 3;
    float4 v0 = __ldcs(xv + 0);
    float4 v1 = __ldcs(xv + 1);
    float4 v2 = __ldcs(xv + 2);

    float cx[PPT] = { v0.x, v0.w, v1.z, v2.y };
    float cy[PPT] = { v0.y, v1.x, v1.w, v2.z };
    float cz[PPT] = { v0.z, v1.y, v2.x, v2.w };

    uint4 cc[PPT];
    float o0[PPT], o1[PPT], o2[PPT];
#pragma unroll
    for (int i = 0; i < PPT; i++) {
        float r0 = cx[i] * 63.0f;
        float r1 = cy[i] * 63.0f;
        float r2 = cz[i] * 63.0f;
        float f0 = floorf(r0), f1 = floorf(r1), f2 = floorf(r2);
        o0[i] = r0 - f0; o1[i] = r1 - f1; o2[i] = r2 - f2;
        int base = ((int)f0 << 12) | ((int)f1 << 6) | (int)f2;
        cc[i] = __ldg(cp + base);
    }

    float4 res;
    float* resp = reinterpret_cast<float*>(&res);
#pragma unroll
    for (int i = 0; i < PPT; i++) {
        float2 f00 = __half22float2(*reinterpret_cast<__half2*>(&cc[i].x)); // c000,c001
        float2 f01 = __half22float2(*reinterpret_cast<__half2*>(&cc[i].y)); // c010,c011
        float2 f10 = __half22float2(*reinterpret_cast<__half2*>(&cc[i].z)); // c100,c101
        float2 f11 = __half22float2(*reinterpret_cast<__half2*>(&cc[i].w)); // c110,c111

        float a00 = f00.x + (f10.x - f00.x) * o0[i];
        float a01 = f00.y + (f10.y - f00.y) * o0[i];
        float a10 = f01.x + (f11.x - f01.x) * o0[i];
        float a11 = f01.y + (f11.y - f01.y) * o0[i];

        float b0 = a00 + (a10 - a00) * o1[i];
        float b1 = a01 + (a11 - a01) * o1[i];
        resp[i] = b0 + (b1 - b0) * o2[i];
    }

    __stcs(reinterpret_cast<float4*>(out) + t, res);
}

// ---- host: forked-stream overlap (resources created once at load; no device
// memory allocation; per-call work is identical and graph-capturable) ----

static cudaStream_t g_s2;
static cudaEvent_t  g_fork;
static cudaEvent_t  g_done[N_CHUNKS];

namespace {
struct StreamInit {
    StreamInit() {
        cudaStreamCreateWithFlags(&g_s2, cudaStreamNonBlocking);
        cudaEventCreateWithFlags(&g_fork, cudaEventDisableTiming);
        for (int i = 0; i < N_CHUNKS; i++)
            cudaEventCreateWithFlags(&g_done[i], cudaEventDisableTiming);
    }
};
StreamInit g_stream_init;
}

extern "C" void kernel_launch(void* const* d_in, const int* in_sizes, int n_in,
                              void* d_out, int out_size)
{
    const float* y    = (const float*)d_in[0];
    const float* xnew = (const float*)d_in[1];
    float* out        = (float*)d_out;

    const int tPerChunk = (BATCHES_PER_CHUNK * M_) / PPT;   // 442,368
    const int blocksPerChunk = tPerChunk / 256;             // 1728

    // fork: s2 joins the capture via the event recorded on the legacy stream
    cudaEventRecord(g_fork, 0);
    cudaStreamWaitEvent(g_s2, g_fork, 0);

    // prepack chunks on s2, each followed by a completion event
    for (int c = 0; c < N_CHUNKS; c++) {
        prepack_kernel<<<BATCHES_PER_CHUNK * D_, 256, 0, g_s2>>>(y, c * BATCHES_PER_CHUNK);
        cudaEventRecord(g_done[c], g_s2);
    }

    // interp chunks on the main stream, each gated on its prepack chunk
    for (int c = 0; c < N_CHUNKS; c++) {
        cudaStreamWaitEvent(0, g_done[c], 0);
        interp_kernel<<<blocksPerChunk, 256>>>(xnew, out, c * tPerChunk);
    }
}

// round 14
// speedup vs baseline: 1.2553x; 1.2553x over previous
#include <cuda_runtime.h>
#include <cuda_fp16.h>

// LinearInterpolator: B=8, grid 64^3 fp32, M=96^3 query points, trilinear.
// inputs: d_in[0]=y (8*64^3 fp32), d_in[1]=xnew (8*M*3 fp32)
// output: d_out = 8*M fp32
//
// fp16 8-corner pack (16B/cell, 32 MB, L2-resident) + single LDG.128 gather
// per point (interp at its L1tex wavefront floor; R11-R13 falsified deeper
// MLP / async staging / stream overlap). Prepack: half-plane smem tiles,
// 1024 blocks for latency hiding.

static constexpr int B_ = 8;
static constexpr int D_ = 64;
static constexpr int GRID3 = D_ * D_ * D_;        // 262144 = 2^18
static constexpr int M_ = 96 * 96 * 96;           // 884736
static constexpr int PPT = 4;                     // points per thread (interp)

// cell layout (16B): h2{c000,c001} h2{c010,c011} h2{c100,c101} h2{c110,c111}
__device__ uint4 g_pack[B_ * GRID3];              // 32 MB static scratch

__device__ __forceinline__ unsigned pack2(float a, float b)
{
    __half2 h = __floats2half2_rn(a, b);
    return *reinterpret_cast<unsigned*>(&h);
}

// One block per (batch, i0, i1-half). smem tile: 33 rows x 64 cols per plane
// (row 32 is the clamped i1+1 boundary row). 1024 blocks total.
static constexpr int HROWS = 33;

__global__ __launch_bounds__(256)
void prepack_kernel(const float* __restrict__ y)
{
    __shared__ float P0[HROWS * D_];              // 8.25 KB
    __shared__ float P1[HROWS * D_];              // 8.25 KB

    const int half = blockIdx.x & 1;
    const int i0   = (blockIdx.x >> 1) & 63;
    const int b    = blockIdx.x >> 7;
    const int i0p  = min(i0 + 1, D_ - 1);
    const int i1h  = half << 5;                   // 0 or 32
    const int tid  = threadIdx.x;

    const float* __restrict__ pl0 = y + ((size_t)b << 18) + (i0  << 12);
    const float* __restrict__ pl1 = y + ((size_t)b << 18) + (i0p << 12);

    // load 33 rows x 64 floats = 528 float4 per plane, rows clamped at 63
    float4* s0 = reinterpret_cast<float4*>(P0);
    float4* s1 = reinterpret_cast<float4*>(P1);
#pragma unroll
    for (int k = 0; k < 3; k++) {
        int v = tid + 256 * k;                    // float4 index within tile
        if (v < HROWS * 16) {
            int r = v >> 4;                       // local row 0..32
            int c = v & 15;                       // float4 col
            int g = min(i1h + r, D_ - 1);         // clamped global i1
            s0[v] = reinterpret_cast<const float4*>(pl0 + (g << 6))[c];
            s1[v] = reinterpret_cast<const float4*>(pl1 + (g << 6))[c];
        }
    }
    __syncthreads();

    const int i2  = tid & 63;
    const int i2p = min(i2 + 1, D_ - 1);
    const int jb  = (tid >> 6) << 3;              // local row base: 0,8,16,24

    uint4* __restrict__ dst = g_pack + ((size_t)b << 18) + (i0 << 12)
                            + ((i1h + jb) << 6) + i2;

    float a0 = P0[(jb << 6) + i2],  a1 = P0[(jb << 6) + i2p];
    float e0 = P1[(jb << 6) + i2],  e1 = P1[(jb << 6) + i2p];

#pragma unroll
    for (int j = 0; j < 8; j++) {
        const int rn = jb + j + 1;                // <= 32, in-tile (pre-clamped)
        const float c0 = P0[(rn << 6) + i2], c1 = P0[(rn << 6) + i2p];
        const float d0 = P1[(rn << 6) + i2], d1 = P1[(rn << 6) + i2p];

        uint4 cc;
        cc.x = pack2(a0, a1);     // c000, c001
        cc.y = pack2(c0, c1);     // c010, c011
        cc.z = pack2(e0, e1);     // c100, c101
        cc.w = pack2(d0, d1);     // c110, c111
        dst[j << 6] = cc;

        a0 = c0; a1 = c1; e0 = d0; e1 = d1;
    }
}

// Interp: R8 configuration (best measured: 40.7 us).
__global__ __launch_bounds__(256)
void interp_kernel(const float* __restrict__ xnew,
                   float* __restrict__ out)
{
    const int t = blockIdx.x * blockDim.x + threadIdx.x;
    const int totalT = (B_ * M_) / PPT;
    if (t >= totalT) return;

    const int p0 = t * PPT;
    const int b  = p0 / M_;                       // M_ % 4 == 0: same batch
    const uint4* __restrict__ cp = g_pack + ((size_t)b << 18);

    const float4* __restrict__ xv = reinterpret_cast<const float4*>(xnew) + (size_t)t * 3;
    float4 v0 = __ldcs(xv + 0);
    float4 v1 = __ldcs(xv + 1);
    float4 v2 = __ldcs(xv + 2);

    float cx[PPT] = { v0.x, v0.w, v1.z, v2.y };
    float cy[PPT] = { v0.y, v1.x, v1.w, v2.z };
    float cz[PPT] = { v0.z, v1.y, v2.x, v2.w };

    uint4 cc[PPT];
    float o0[PPT], o1[PPT], o2[PPT];
#pragma unroll
    for (int i = 0; i < PPT; i++) {
        float r0 = cx[i] * 63.0f;
        float r1 = cy[i] * 63.0f;
        float r2 = cz[i] * 63.0f;
        float f0 = floorf(r0), f1 = floorf(r1), f2 = floorf(r2);
        o0[i] = r0 - f0; o1[i] = r1 - f1; o2[i] = r2 - f2;
        int base = ((int)f0 << 12) | ((int)f1 << 6) | (int)f2;
        cc[i] = __ldg(cp + base);
    }

    float4 res;
    float* resp = reinterpret_cast<float*>(&res);
#pragma unroll
    for (int i = 0; i < PPT; i++) {
        float2 f00 = __half22float2(*reinterpret_cast<__half2*>(&cc[i].x)); // c000,c001
        float2 f01 = __half22float2(*reinterpret_cast<__half2*>(&cc[i].y)); // c010,c011
        float2 f10 = __half22float2(*reinterpret_cast<__half2*>(&cc[i].z)); // c100,c101
        float2 f11 = __half22float2(*reinterpret_cast<__half2*>(&cc[i].w)); // c110,c111

        float a00 = f00.x + (f10.x - f00.x) * o0[i];
        float a01 = f00.y + (f10.y - f00.y) * o0[i];
        float a10 = f01.x + (f11.x - f01.x) * o0[i];
        float a11 = f01.y + (f11.y - f01.y) * o0[i];

        float b0 = a00 + (a10 - a00) * o1[i];
        float b1 = a01 + (a11 - a01) * o1[i];
        resp[i] = b0 + (b1 - b0) * o2[i];
    }

    __stcs(reinterpret_cast<float4*>(out) + t, res);
}

extern "C" void kernel_launch(void* const* d_in, const int* in_sizes, int n_in,
                              void* d_out, int out_size)
{
    const float* y    = (const float*)d_in[0];
    const float* xnew = (const float*)d_in[1];
    float* out        = (float*)d_out;

    prepack_kernel<<<B_ * D_ * 2, 256>>>(y);      // 1024 blocks

    const int totalT = (B_ * M_) / PPT;           // 1,769,472
    interp_kernel<<<totalT / 256, 256>>>(xnew, out);   // 6912 blocks
}